// round 4
// baseline (speedup 1.0000x reference)
#include <cuda_runtime.h>
#include <cstdint>
#include <math.h>

// Problem constants: B=8, T=2048, D=1024, E=8 -> BT=16384
#define D_DIM 1024
#define E_DIM 8
#define BT_MAX 16384

__device__ float g_mix[BT_MAX * E_DIM];

// Arch-specific feature gate: true only when compiling a cubin phase that
// supports tcgen05 (sm_103a / sm_100a). On the family-generic sm_103 phase
// this is 0 and the tcgen05 kernel compiles to an empty body.
#if defined(__CUDA_ARCH__) && (defined(__CUDA_ARCH_FEAT_SM103_ALL) || defined(__CUDA_ARCH_FEAT_SM100_ALL))
#define HAS_TCGEN05 1
#else
#define HAS_TCGEN05 0
#endif

// ===========================================================================
// Common PTX helpers
// ===========================================================================
__device__ __forceinline__ uint32_t smem_u32(const void* p) {
    uint32_t a;
    asm("{ .reg .u64 t; cvta.to.shared.u64 t, %1; cvt.u32.u64 %0, t; }" : "=r"(a) : "l"(p));
    return a;
}

#define CP_ASYNC16(dst, src) \
    asm volatile("cp.async.cg.shared.global [%0], [%1], 16;" :: "r"(dst), "l"(src) : "memory")

#define MBARRIER_INIT(addr, cnt) \
    asm volatile("mbarrier.init.shared.b64 [%0], %1;" :: "r"(addr), "r"(cnt) : "memory")

#define MBARRIER_WAIT_PARITY(addr, ph) do {                                      \
    uint32_t _m = (addr); uint32_t _p = (ph); uint32_t _d;                       \
    asm volatile("{\n\t.reg .pred p;\n\t"                                        \
        "mbarrier.try_wait.parity.acquire.cta.shared::cta.b64 p, [%1], %2;\n\t"  \
        "selp.b32 %0, 1, 0, p;\n\t}"                                             \
        : "=r"(_d) : "r"(_m), "r"(_p) : "memory");                               \
    if (!_d) {                                                                   \
        asm volatile("{\n\t.reg .pred P1;\n\t"                                   \
        "W%=:\n\t"                                                               \
        "mbarrier.try_wait.parity.acquire.cta.shared::cta.b64 P1, [%0], %1, 0x989680;\n\t" \
        "@P1 bra.uni DN%=;\n\t"                                                  \
        "bra.uni W%=;\n\t"                                                       \
        "DN%=:\n\t}" :: "r"(_m), "r"(_p) : "memory");                            \
    } } while (0)

// fp32 -> tf32 with round-to-nearest
__device__ __forceinline__ uint32_t f2tf32(float f) {
    uint32_t u; asm("cvt.rna.tf32.f32 %0, %1;" : "=r"(u) : "f"(f)); return u;
}

// warp-level tf32 mma (sm_80+; legal on family-generic targets)
__device__ __forceinline__ void mma16n8k8(float* d, const uint32_t* a, const uint32_t* b) {
    asm volatile("mma.sync.aligned.m16n8k8.row.col.f32.tf32.tf32.f32 "
        "{%0,%1,%2,%3}, {%4,%5,%6,%7}, {%8,%9}, {%0,%1,%2,%3};"
        : "+f"(d[0]), "+f"(d[1]), "+f"(d[2]), "+f"(d[3])
        : "r"(a[0]), "r"(a[1]), "r"(a[2]), "r"(a[3]), "r"(b[0]), "r"(b[1]));
}

// ===========================================================================
// Kernel 1: routing (arch-generic; verified in R1)
// ===========================================================================
__global__ __launch_bounds__(128) void routing_kernel(
    const float* __restrict__ x,
    const float* __restrict__ Wf, const float* __restrict__ bf,
    const float* __restrict__ Wt, const float* __restrict__ bt,
    const float* __restrict__ alpha, int BT)
{
    int warp = blockIdx.x * (blockDim.x >> 5) + (threadIdx.x >> 5);
    int lane = threadIdx.x & 31;
    if (warp >= BT) return;

    const float* xr = x + (size_t)warp * D_DIM;
    float xv[32];
#pragma unroll
    for (int j = 0; j < 32; ++j) xv[j] = xr[lane + 32 * j];

    float dots[16];
#pragma unroll
    for (int r = 0; r < 16; ++r) {
        const float* w = (r < 8) ? (Wt + r * D_DIM) : (Wf + (r - 8) * D_DIM);
        float s = 0.0f;
#pragma unroll
        for (int j = 0; j < 32; ++j) s += xv[j] * w[lane + 32 * j];
#pragma unroll
        for (int off = 16; off > 0; off >>= 1)
            s += __shfl_xor_sync(0xffffffffu, s, off);
        dots[r] = s;
    }

    float tl[8], fl[8];
#pragma unroll
    for (int e = 0; e < 8; ++e) { tl[e] = dots[e] + bt[e]; fl[e] = dots[8 + e] + bf[e]; }

    float v0 = tl[0]; int i0 = 0;
    float v1 = -INFINITY; int i1 = -1;
#pragma unroll
    for (int e = 1; e < 8; ++e) {
        if (tl[e] > v0) { v1 = v0; i1 = i0; v0 = tl[e]; i0 = e; }
        else if (tl[e] > v1) { v1 = tl[e]; i1 = e; }
    }
    float p1 = expf(v1 - v0);
    float sv0 = 1.0f / (1.0f + p1);
    float sv1 = p1 * sv0;

    float mf = fl[0];
#pragma unroll
    for (int e = 1; e < 8; ++e) mf = fmaxf(mf, fl[e]);
    float ef[8]; float se = 0.0f;
#pragma unroll
    for (int e = 0; e < 8; ++e) { ef[e] = expf(fl[e] - mf); se += ef[e]; }
    float inv_se = 1.0f / se;

    float a = 1.0f / (1.0f + expf(-alpha[0]));
    float one_m_a = 1.0f - a;

#pragma unroll
    for (int e = 0; e < 8; ++e) {
        float tp = (e == i0) ? sv0 : ((e == i1) ? sv1 : 0.0f);
        float m = a * tp + one_m_a * ef[e] * inv_se;
        if (lane == e) g_mix[(size_t)warp * E_DIM + e] = m;
    }
}

// ===========================================================================
// Kernel T: tcgen05 tf32 path (active only on arch-specific cubin)
// ===========================================================================
#define T_BM 128
#define T_BN 64
#define T_BK 32
#define T_KSTEPS (D_DIM / T_BK)

#define SM_FULL0   0
#define SM_FULL1   8
#define SM_EMPTY0  16
#define SM_EMPTY1  24
#define SM_DONE    32
#define SM_TMEMPTR 64
#define SM_BGS     128
#define SM_A       4096
#define SM_B       36864
#define SMEM_TOTAL 167936

static __device__ __forceinline__ uint32_t swz(uint32_t off) {
    return off ^ ((off >> 3) & 0x70);
}

__global__ __launch_bounds__(256, 1) void moe_gate_tc(
    const float* __restrict__ x,
    const float* __restrict__ Wg,
    const float* __restrict__ bg,
    float* __restrict__ out)
{
#if HAS_TCGEN05
    extern __shared__ char smem[];
    const uint32_t sb = smem_u32(smem);
    const int tid = threadIdx.x;
    const int wid = tid >> 5;
    const int lane = tid & 31;
    const int m0 = blockIdx.y * T_BM;
    const int n0 = blockIdx.x * T_BN;

    constexpr uint32_t IDESC_TF32 =
        (1u << 4) | (2u << 7) | (2u << 10) | ((T_BN / 8) << 17) | ((T_BM / 16) << 24);

    if (tid == 0) {
        MBARRIER_INIT(sb + SM_FULL0, 64);
        MBARRIER_INIT(sb + SM_FULL1, 64);
        MBARRIER_INIT(sb + SM_EMPTY0, 1);
        MBARRIER_INIT(sb + SM_EMPTY1, 1);
        MBARRIER_INIT(sb + SM_DONE, 1);
    }
    __syncthreads();
    if (wid == 6) {
        asm volatile("tcgen05.alloc.cta_group::1.sync.aligned.shared::cta.b32 [%0], %1;"
            :: "r"(sb + SM_TMEMPTR), "r"(512) : "memory");
        asm volatile("tcgen05.relinquish_alloc_permit.cta_group::1.sync.aligned;");
    }
    __syncthreads();
    uint32_t tmem;
    asm volatile("ld.shared.b32 %0, [%1];" : "=r"(tmem) : "r"(sb + SM_TMEMPTR));

    if (wid >= 4 && wid < 6) {
        const int p = tid - 128;
        int pe = 1;
        for (int s = 0; s < T_KSTEPS; ++s) {
            const int buf = s & 1;
            MBARRIER_WAIT_PARITY(sb + (buf ? SM_EMPTY1 : SM_EMPTY0), pe);
            if (buf) pe ^= 1;
            const uint32_t aBase = sb + SM_A + buf * 16384;
            const uint32_t bBase = sb + SM_B + buf * 65536;
            const int k0 = s * T_BK;
#pragma unroll
            for (int i = 0; i < 16; ++i) {
                const int c = p + i * 64;
                const int row = c >> 3, q = c & 7;
                const uint32_t dst = aBase + swz((uint32_t)(row * 128 + q * 16));
                CP_ASYNC16(dst, x + (size_t)(m0 + row) * D_DIM + k0 + q * 4);
            }
#pragma unroll
            for (int i = 0; i < 64; ++i) {
                const int c = p + i * 64;
                const int e = c >> 9;
                const int row = (c >> 3) & 63, q = c & 7;
                const uint32_t dst = bBase + e * 8192 + swz((uint32_t)(row * 128 + q * 16));
                CP_ASYNC16(dst, Wg + (size_t)e * (D_DIM * D_DIM)
                                   + (size_t)(n0 + row) * D_DIM + k0 + q * 4);
            }
            asm volatile("cp.async.mbarrier.arrive.noinc.shared::cta.b64 [%0];"
                :: "r"(sb + (buf ? SM_FULL1 : SM_FULL0)) : "memory");
        }
    } else if (tid == 192) {
        int pf = 0;
        for (int s = 0; s < T_KSTEPS; ++s) {
            const int buf = s & 1;
            MBARRIER_WAIT_PARITY(sb + (buf ? SM_FULL1 : SM_FULL0), pf);
            if (buf) pf ^= 1;
            asm volatile("fence.proxy.async.shared::cta;" ::: "memory");
            const uint32_t aB = sb + SM_A + buf * 16384;
            const uint32_t bB = sb + SM_B + buf * 65536;
            const uint64_t ad = 0x4000404000010000ull | (uint64_t)((aB >> 4) & 0x3FFF);
#pragma unroll
            for (int e = 0; e < 8; ++e) {
                const uint64_t bd = 0x4000404000010000ull
                                  | (uint64_t)(((bB + e * 8192) >> 4) & 0x3FFF);
#pragma unroll
                for (int kk = 0; kk < 4; ++kk) {
                    const uint32_t en = !(s == 0 && kk == 0) ? 1u : 0u;
                    asm volatile("{\n\t.reg .pred p;\n\tsetp.ne.u32 p, %5, 0;\n\t"
                        "tcgen05.mma.cta_group::1.kind::tf32 [%0], %1, %2, %3, {%4,%4,%4,%4}, p;\n\t}"
                        :: "r"(tmem + e * 64), "l"(ad + kk * 2), "l"(bd + kk * 2),
                           "r"(IDESC_TF32), "r"(0u), "r"(en) : "memory");
                }
            }
            asm volatile("tcgen05.commit.cta_group::1.mbarrier::arrive::one.shared::cluster.b64 [%0];"
                :: "r"(sb + (buf ? SM_EMPTY1 : SM_EMPTY0)) : "memory");
        }
        asm volatile("tcgen05.commit.cta_group::1.mbarrier::arrive::one.shared::cluster.b64 [%0];"
            :: "r"(sb + SM_DONE) : "memory");
    } else if (wid < 4) {
        const int m = m0 + wid * 32 + lane;
        float* bgs = (float*)(smem + SM_BGS);
        for (int i = tid; i < 512; i += 128)
            bgs[i] = bg[(size_t)(i >> 6) * D_DIM + n0 + (i & 63)];
        asm volatile("bar.sync 1, 128;" ::: "memory");

        float mixv[8];
        *(float4*)&mixv[0] = *(const float4*)(g_mix + (size_t)m * 8);
        *(float4*)&mixv[4] = *(const float4*)(g_mix + (size_t)m * 8 + 4);

        float accO[64];
#pragma unroll
        for (int c = 0; c < 64; ++c) accO[c] = 0.0f;

        MBARRIER_WAIT_PARITY(sb + SM_DONE, 0);
        asm volatile("tcgen05.fence::after_thread_sync;" ::: "memory");

#pragma unroll
        for (int e = 0; e < 8; ++e) {
            const float mx = mixv[e];
#pragma unroll
            for (int h = 0; h < 2; ++h) {
                uint32_t d[32];
                asm volatile("tcgen05.ld.sync.aligned.32x32b.x32.b32 "
                    "{%0,%1,%2,%3,%4,%5,%6,%7,%8,%9,%10,%11,%12,%13,%14,%15,"
                    "%16,%17,%18,%19,%20,%21,%22,%23,%24,%25,%26,%27,%28,%29,%30,%31}, [%32];"
                    : "=r"(d[0]),"=r"(d[1]),"=r"(d[2]),"=r"(d[3]),"=r"(d[4]),"=r"(d[5]),
                      "=r"(d[6]),"=r"(d[7]),"=r"(d[8]),"=r"(d[9]),"=r"(d[10]),"=r"(d[11]),
                      "=r"(d[12]),"=r"(d[13]),"=r"(d[14]),"=r"(d[15]),"=r"(d[16]),"=r"(d[17]),
                      "=r"(d[18]),"=r"(d[19]),"=r"(d[20]),"=r"(d[21]),"=r"(d[22]),"=r"(d[23]),
                      "=r"(d[24]),"=r"(d[25]),"=r"(d[26]),"=r"(d[27]),"=r"(d[28]),"=r"(d[29]),
                      "=r"(d[30]),"=r"(d[31]) : "r"(tmem + e * 64 + h * 32));
                asm volatile("tcgen05.wait::ld.sync.aligned;" ::: "memory");
#pragma unroll
                for (int c = 0; c < 32; ++c) {
                    const float z = __uint_as_float(d[c]) + bgs[e * 64 + h * 32 + c];
                    accO[h * 32 + c] += mx / (1.0f + __expf(-z));
                }
            }
        }

        float* orow = out + (size_t)m * D_DIM + n0;
#pragma unroll
        for (int v = 0; v < 16; ++v) {
            float4 o = make_float4(accO[4 * v], accO[4 * v + 1],
                                   accO[4 * v + 2], accO[4 * v + 3]);
            __stcs((float4*)(orow + 4 * v), o);
        }
    }

    __syncthreads();
    if (wid == 6)
        asm volatile("tcgen05.dealloc.cta_group::1.sync.aligned.b32 %0, %1;"
            :: "r"(tmem), "r"(512));
#endif // HAS_TCGEN05
}

// ===========================================================================
// Kernel F: warp-level tf32 mma.sync fallback (active on family-generic cubin)
//   CTA tile 128x128, 8 warps (2x4), warp tile 64x32, m16n8k8, cp.async 2-stage.
// ===========================================================================
#define F_BM 128
#define F_BN 128
#define F_BK 16
#define F_ST 20   // padded smem row stride (floats) -> conflict-free frag LDS

__global__ __launch_bounds__(256, 1) void moe_gate_mma(
    const float* __restrict__ x,
    const float* __restrict__ Wg,
    const float* __restrict__ bg,
    float* __restrict__ out)
{
#if !HAS_TCGEN05
    __shared__ __align__(16) float As[2 * F_BM * F_ST];
    __shared__ __align__(16) float Bs[2 * F_BM * F_ST];
    __shared__ __align__(16) float mixs[F_BM * E_DIM];

    const int tid = threadIdx.x;
    const int warp = tid >> 5, lane = tid & 31;
    const int wm = (warp & 1) * 64;
    const int wn = (warp >> 1) * 32;
    const int g = lane >> 2, tg = lane & 3;
    const int m0 = blockIdx.y * F_BM, n0 = blockIdx.x * F_BN;

    const uint32_t sAs = smem_u32(As);
    const uint32_t sBs = smem_u32(Bs);

    // stage mix tile: 128x8 floats = 256 float4
    ((float4*)mixs)[tid] = ((const float4*)(g_mix + (size_t)m0 * E_DIM))[tid];
    __syncthreads();

    float accOut[4][4][4];
#pragma unroll
    for (int a = 0; a < 4; ++a)
#pragma unroll
        for (int b = 0; b < 4; ++b)
#pragma unroll
            for (int c = 0; c < 4; ++c) accOut[a][b][c] = 0.0f;

#define F_LOAD_STAGE(st, k0, Bsrc) do {                                          \
    _Pragma("unroll")                                                            \
    for (int it = 0; it < 2; ++it) {                                             \
        const int i = tid + it * 256;                                            \
        const int r = i >> 2, q = i & 3;                                         \
        CP_ASYNC16(sAs + (uint32_t)(((st) * F_BM * F_ST + r * F_ST + q * 4) * 4),\
                   x + (size_t)(m0 + r) * D_DIM + (k0) + q * 4);                 \
        CP_ASYNC16(sBs + (uint32_t)(((st) * F_BM * F_ST + r * F_ST + q * 4) * 4),\
                   (Bsrc) + (size_t)r * D_DIM + (k0) + q * 4);                   \
    }                                                                            \
    asm volatile("cp.async.commit_group;" ::: "memory");                         \
} while (0)

    for (int e = 0; e < E_DIM; ++e) {
        const float* Bsrc = Wg + (size_t)e * D_DIM * D_DIM + (size_t)n0 * D_DIM;

        float acc[4][4][4];
#pragma unroll
        for (int a = 0; a < 4; ++a)
#pragma unroll
            for (int b = 0; b < 4; ++b)
#pragma unroll
                for (int c = 0; c < 4; ++c) acc[a][b][c] = 0.0f;

        F_LOAD_STAGE(0, 0, Bsrc);

        for (int ks = 0; ks < D_DIM / F_BK; ++ks) {
            const int cur = ks & 1;
            if (ks < D_DIM / F_BK - 1) {
                F_LOAD_STAGE(cur ^ 1, (ks + 1) * F_BK, Bsrc);
                asm volatile("cp.async.wait_group 1;" ::: "memory");
            } else {
                asm volatile("cp.async.wait_group 0;" ::: "memory");
            }
            __syncthreads();

            const float* Af = As + cur * F_BM * F_ST;
            const float* Bf = Bs + cur * F_BM * F_ST;
#pragma unroll
            for (int kk = 0; kk < F_BK; kk += 8) {
                uint32_t afr[4][4], bfr[4][2];
#pragma unroll
                for (int mf = 0; mf < 4; ++mf) {
                    const int r = wm + mf * 16 + g;
                    afr[mf][0] = f2tf32(Af[r * F_ST + kk + tg]);
                    afr[mf][1] = f2tf32(Af[(r + 8) * F_ST + kk + tg]);
                    afr[mf][2] = f2tf32(Af[r * F_ST + kk + tg + 4]);
                    afr[mf][3] = f2tf32(Af[(r + 8) * F_ST + kk + tg + 4]);
                }
#pragma unroll
                for (int nf = 0; nf < 4; ++nf) {
                    const int c = wn + nf * 8 + g;
                    bfr[nf][0] = f2tf32(Bf[c * F_ST + kk + tg]);
                    bfr[nf][1] = f2tf32(Bf[c * F_ST + kk + tg + 4]);
                }
#pragma unroll
                for (int mf = 0; mf < 4; ++mf)
#pragma unroll
                    for (int nf = 0; nf < 4; ++nf)
                        mma16n8k8(acc[mf][nf], afr[mf], bfr[nf]);
            }
            __syncthreads();
        }

        // fold: accOut += mix[m,e] * sigmoid(acc + bg[e,n])
#pragma unroll
        for (int mf = 0; mf < 4; ++mf) {
            const int r = wm + mf * 16 + g;
            const float mx0 = mixs[r * E_DIM + e];
            const float mx1 = mixs[(r + 8) * E_DIM + e];
#pragma unroll
            for (int nf = 0; nf < 4; ++nf) {
                const int c = wn + nf * 8 + 2 * tg;
                const float b0 = __ldg(bg + (size_t)e * D_DIM + n0 + c);
                const float b1 = __ldg(bg + (size_t)e * D_DIM + n0 + c + 1);
                accOut[mf][nf][0] += mx0 / (1.0f + __expf(-(acc[mf][nf][0] + b0)));
                accOut[mf][nf][1] += mx0 / (1.0f + __expf(-(acc[mf][nf][1] + b1)));
                accOut[mf][nf][2] += mx1 / (1.0f + __expf(-(acc[mf][nf][2] + b0)));
                accOut[mf][nf][3] += mx1 / (1.0f + __expf(-(acc[mf][nf][3] + b1)));
            }
        }
    }

    // write 128x128 tile
#pragma unroll
    for (int mf = 0; mf < 4; ++mf) {
        const int r0 = m0 + wm + mf * 16 + g;
#pragma unroll
        for (int nf = 0; nf < 4; ++nf) {
            const int c = n0 + wn + nf * 8 + 2 * tg;
            *(float2*)(out + (size_t)r0 * D_DIM + c) =
                make_float2(accOut[mf][nf][0], accOut[mf][nf][1]);
            *(float2*)(out + (size_t)(r0 + 8) * D_DIM + c) =
                make_float2(accOut[mf][nf][2], accOut[mf][nf][3]);
        }
    }
#endif // !HAS_TCGEN05
}

// ===========================================================================
// Inputs: x, Wg, bg, Wf, bf, Wt, bt, alpha, num
// ===========================================================================
extern "C" void kernel_launch(void* const* d_in, const int* in_sizes, int n_in,
                              void* d_out, int out_size)
{
    const float* x     = (const float*)d_in[0];
    const float* Wg    = (const float*)d_in[1];
    const float* bg    = (const float*)d_in[2];
    const float* Wf    = (const float*)d_in[3];
    const float* bf    = (const float*)d_in[4];
    const float* Wt    = (const float*)d_in[5];
    const float* bt    = (const float*)d_in[6];
    const float* alpha = (const float*)d_in[7];
    float* out = (float*)d_out;

    const int BT = in_sizes[0] / D_DIM;   // 16384

    cudaFuncSetAttribute(moe_gate_tc,
                         cudaFuncAttributeMaxDynamicSharedMemorySize, SMEM_TOTAL);

    routing_kernel<<<(BT + 3) / 4, 128>>>(x, Wf, bf, Wt, bt, alpha, BT);

    // tcgen05 path (no-op on family-generic cubin)
    dim3 gridT(D_DIM / T_BN, BT / T_BM);           // (16, 128)
    moe_gate_tc<<<gridT, 256, SMEM_TOTAL>>>(x, Wg, bg, out);

    // mma.sync fallback (no-op on arch-specific cubin)
    dim3 gridF(D_DIM / F_BN, BT / F_BM);           // (8, 128)
    moe_gate_mma<<<gridF, 256>>>(x, Wg, bg, out);
}

// round 5
// speedup vs baseline: 1.0011x; 1.0011x over previous
#include <cuda_runtime.h>
#include <cstdint>
#include <math.h>

// Problem constants: B=8, T=2048, D=1024, E=8 -> BT=16384
#define D_DIM 1024
#define E_DIM 8
#define BT_MAX 16384

__device__ float g_mix[BT_MAX * E_DIM];

// Arch-specific feature gate: true only when compiling a cubin phase that
// supports tcgen05 (sm_103a / sm_100a). On the family-generic sm_103 phase
// this is 0 and the tcgen05 kernel compiles to an empty body.
#if defined(__CUDA_ARCH__) && (defined(__CUDA_ARCH_FEAT_SM103_ALL) || defined(__CUDA_ARCH_FEAT_SM100_ALL))
#define HAS_TCGEN05 1
#else
#define HAS_TCGEN05 0
#endif

// ===========================================================================
// Common PTX helpers
// ===========================================================================
__device__ __forceinline__ uint32_t smem_u32(const void* p) {
    uint32_t a;
    asm("{ .reg .u64 t; cvta.to.shared.u64 t, %1; cvt.u32.u64 %0, t; }" : "=r"(a) : "l"(p));
    return a;
}

#define CP_ASYNC16(dst, src) \
    asm volatile("cp.async.cg.shared.global [%0], [%1], 16;" :: "r"(dst), "l"(src) : "memory")

#define MBARRIER_INIT(addr, cnt) \
    asm volatile("mbarrier.init.shared.b64 [%0], %1;" :: "r"(addr), "r"(cnt) : "memory")

#define MBARRIER_WAIT_PARITY(addr, ph) do {                                      \
    uint32_t _m = (addr); uint32_t _p = (ph); uint32_t _d;                       \
    asm volatile("{\n\t.reg .pred p;\n\t"                                        \
        "mbarrier.try_wait.parity.acquire.cta.shared::cta.b64 p, [%1], %2;\n\t"  \
        "selp.b32 %0, 1, 0, p;\n\t}"                                             \
        : "=r"(_d) : "r"(_m), "r"(_p) : "memory");                               \
    if (!_d) {                                                                   \
        asm volatile("{\n\t.reg .pred P1;\n\t"                                   \
        "W%=:\n\t"                                                               \
        "mbarrier.try_wait.parity.acquire.cta.shared::cta.b64 P1, [%0], %1, 0x989680;\n\t" \
        "@P1 bra.uni DN%=;\n\t"                                                  \
        "bra.uni W%=;\n\t"                                                       \
        "DN%=:\n\t}" :: "r"(_m), "r"(_p) : "memory");                            \
    } } while (0)

// fp32 -> tf32 with round-to-nearest
__device__ __forceinline__ uint32_t f2tf32(float f) {
    uint32_t u; asm("cvt.rna.tf32.f32 %0, %1;" : "=r"(u) : "f"(f)); return u;
}

// warp-level tf32 mma (sm_80+; legal on family-generic targets)
__device__ __forceinline__ void mma16n8k8(float* d, const uint32_t* a, const uint32_t* b) {
    asm volatile("mma.sync.aligned.m16n8k8.row.col.f32.tf32.tf32.f32 "
        "{%0,%1,%2,%3}, {%4,%5,%6,%7}, {%8,%9}, {%0,%1,%2,%3};"
        : "+f"(d[0]), "+f"(d[1]), "+f"(d[2]), "+f"(d[3])
        : "r"(a[0]), "r"(a[1]), "r"(a[2]), "r"(a[3]), "r"(b[0]), "r"(b[1]));
}

// ===========================================================================
// Kernel 1: routing (arch-generic; verified in R1)
// ===========================================================================
__global__ __launch_bounds__(128) void routing_kernel(
    const float* __restrict__ x,
    const float* __restrict__ Wf, const float* __restrict__ bf,
    const float* __restrict__ Wt, const float* __restrict__ bt,
    const float* __restrict__ alpha, int BT)
{
    int warp = blockIdx.x * (blockDim.x >> 5) + (threadIdx.x >> 5);
    int lane = threadIdx.x & 31;
    if (warp >= BT) return;

    const float* xr = x + (size_t)warp * D_DIM;
    float xv[32];
#pragma unroll
    for (int j = 0; j < 32; ++j) xv[j] = xr[lane + 32 * j];

    float dots[16];
#pragma unroll
    for (int r = 0; r < 16; ++r) {
        const float* w = (r < 8) ? (Wt + r * D_DIM) : (Wf + (r - 8) * D_DIM);
        float s = 0.0f;
#pragma unroll
        for (int j = 0; j < 32; ++j) s += xv[j] * w[lane + 32 * j];
#pragma unroll
        for (int off = 16; off > 0; off >>= 1)
            s += __shfl_xor_sync(0xffffffffu, s, off);
        dots[r] = s;
    }

    float tl[8], fl[8];
#pragma unroll
    for (int e = 0; e < 8; ++e) { tl[e] = dots[e] + bt[e]; fl[e] = dots[8 + e] + bf[e]; }

    float v0 = tl[0]; int i0 = 0;
    float v1 = -INFINITY; int i1 = -1;
#pragma unroll
    for (int e = 1; e < 8; ++e) {
        if (tl[e] > v0) { v1 = v0; i1 = i0; v0 = tl[e]; i0 = e; }
        else if (tl[e] > v1) { v1 = tl[e]; i1 = e; }
    }
    float p1 = expf(v1 - v0);
    float sv0 = 1.0f / (1.0f + p1);
    float sv1 = p1 * sv0;

    float mf = fl[0];
#pragma unroll
    for (int e = 1; e < 8; ++e) mf = fmaxf(mf, fl[e]);
    float ef[8]; float se = 0.0f;
#pragma unroll
    for (int e = 0; e < 8; ++e) { ef[e] = expf(fl[e] - mf); se += ef[e]; }
    float inv_se = 1.0f / se;

    float a = 1.0f / (1.0f + expf(-alpha[0]));
    float one_m_a = 1.0f - a;

#pragma unroll
    for (int e = 0; e < 8; ++e) {
        float tp = (e == i0) ? sv0 : ((e == i1) ? sv1 : 0.0f);
        float m = a * tp + one_m_a * ef[e] * inv_se;
        if (lane == e) g_mix[(size_t)warp * E_DIM + e] = m;
    }
}

// ===========================================================================
// Kernel T: tcgen05 tf32 path (active only on arch-specific cubin)
// ===========================================================================
#define T_BM 128
#define T_BN 64
#define T_BK 32
#define T_KSTEPS (D_DIM / T_BK)

#define SM_FULL0   0
#define SM_FULL1   8
#define SM_EMPTY0  16
#define SM_EMPTY1  24
#define SM_DONE    32
#define SM_TMEMPTR 64
#define SM_BGS     128
#define SM_A       4096
#define SM_B       36864
#define SMEM_TOTAL 167936

static __device__ __forceinline__ uint32_t swz(uint32_t off) {
    return off ^ ((off >> 3) & 0x70);
}

__global__ __launch_bounds__(256, 1) void moe_gate_tc(
    const float* __restrict__ x,
    const float* __restrict__ Wg,
    const float* __restrict__ bg,
    float* __restrict__ out)
{
#if HAS_TCGEN05
    extern __shared__ char smem[];
    const uint32_t sb = smem_u32(smem);
    const int tid = threadIdx.x;
    const int wid = tid >> 5;
    const int lane = tid & 31;
    const int m0 = blockIdx.y * T_BM;
    const int n0 = blockIdx.x * T_BN;

    constexpr uint32_t IDESC_TF32 =
        (1u << 4) | (2u << 7) | (2u << 10) | ((T_BN / 8) << 17) | ((T_BM / 16) << 24);

    if (tid == 0) {
        MBARRIER_INIT(sb + SM_FULL0, 64);
        MBARRIER_INIT(sb + SM_FULL1, 64);
        MBARRIER_INIT(sb + SM_EMPTY0, 1);
        MBARRIER_INIT(sb + SM_EMPTY1, 1);
        MBARRIER_INIT(sb + SM_DONE, 1);
    }
    __syncthreads();
    if (wid == 6) {
        asm volatile("tcgen05.alloc.cta_group::1.sync.aligned.shared::cta.b32 [%0], %1;"
            :: "r"(sb + SM_TMEMPTR), "r"(512) : "memory");
        asm volatile("tcgen05.relinquish_alloc_permit.cta_group::1.sync.aligned;");
    }
    __syncthreads();
    uint32_t tmem;
    asm volatile("ld.shared.b32 %0, [%1];" : "=r"(tmem) : "r"(sb + SM_TMEMPTR));

    if (wid >= 4 && wid < 6) {
        const int p = tid - 128;
        int pe = 1;
        for (int s = 0; s < T_KSTEPS; ++s) {
            const int buf = s & 1;
            MBARRIER_WAIT_PARITY(sb + (buf ? SM_EMPTY1 : SM_EMPTY0), pe);
            if (buf) pe ^= 1;
            const uint32_t aBase = sb + SM_A + buf * 16384;
            const uint32_t bBase = sb + SM_B + buf * 65536;
            const int k0 = s * T_BK;
#pragma unroll
            for (int i = 0; i < 16; ++i) {
                const int c = p + i * 64;
                const int row = c >> 3, q = c & 7;
                const uint32_t dst = aBase + swz((uint32_t)(row * 128 + q * 16));
                CP_ASYNC16(dst, x + (size_t)(m0 + row) * D_DIM + k0 + q * 4);
            }
#pragma unroll
            for (int i = 0; i < 64; ++i) {
                const int c = p + i * 64;
                const int e = c >> 9;
                const int row = (c >> 3) & 63, q = c & 7;
                const uint32_t dst = bBase + e * 8192 + swz((uint32_t)(row * 128 + q * 16));
                CP_ASYNC16(dst, Wg + (size_t)e * (D_DIM * D_DIM)
                                   + (size_t)(n0 + row) * D_DIM + k0 + q * 4);
            }
            asm volatile("cp.async.mbarrier.arrive.noinc.shared::cta.b64 [%0];"
                :: "r"(sb + (buf ? SM_FULL1 : SM_FULL0)) : "memory");
        }
    } else if (tid == 192) {
        int pf = 0;
        for (int s = 0; s < T_KSTEPS; ++s) {
            const int buf = s & 1;
            MBARRIER_WAIT_PARITY(sb + (buf ? SM_FULL1 : SM_FULL0), pf);
            if (buf) pf ^= 1;
            asm volatile("fence.proxy.async.shared::cta;" ::: "memory");
            const uint32_t aB = sb + SM_A + buf * 16384;
            const uint32_t bB = sb + SM_B + buf * 65536;
            const uint64_t ad = 0x4000404000010000ull | (uint64_t)((aB >> 4) & 0x3FFF);
#pragma unroll
            for (int e = 0; e < 8; ++e) {
                const uint64_t bd = 0x4000404000010000ull
                                  | (uint64_t)(((bB + e * 8192) >> 4) & 0x3FFF);
#pragma unroll
                for (int kk = 0; kk < 4; ++kk) {
                    const uint32_t en = !(s == 0 && kk == 0) ? 1u : 0u;
                    asm volatile("{\n\t.reg .pred p;\n\tsetp.ne.u32 p, %5, 0;\n\t"
                        "tcgen05.mma.cta_group::1.kind::tf32 [%0], %1, %2, %3, {%4,%4,%4,%4}, p;\n\t}"
                        :: "r"(tmem + e * 64), "l"(ad + kk * 2), "l"(bd + kk * 2),
                           "r"(IDESC_TF32), "r"(0u), "r"(en) : "memory");
                }
            }
            asm volatile("tcgen05.commit.cta_group::1.mbarrier::arrive::one.shared::cluster.b64 [%0];"
                :: "r"(sb + (buf ? SM_EMPTY1 : SM_EMPTY0)) : "memory");
        }
        asm volatile("tcgen05.commit.cta_group::1.mbarrier::arrive::one.shared::cluster.b64 [%0];"
            :: "r"(sb + SM_DONE) : "memory");
    } else if (wid < 4) {
        const int m = m0 + wid * 32 + lane;
        float* bgs = (float*)(smem + SM_BGS);
        for (int i = tid; i < 512; i += 128)
            bgs[i] = bg[(size_t)(i >> 6) * D_DIM + n0 + (i & 63)];
        asm volatile("bar.sync 1, 128;" ::: "memory");

        float mixv[8];
        *(float4*)&mixv[0] = *(const float4*)(g_mix + (size_t)m * 8);
        *(float4*)&mixv[4] = *(const float4*)(g_mix + (size_t)m * 8 + 4);

        float accO[64];
#pragma unroll
        for (int c = 0; c < 64; ++c) accO[c] = 0.0f;

        MBARRIER_WAIT_PARITY(sb + SM_DONE, 0);
        asm volatile("tcgen05.fence::after_thread_sync;" ::: "memory");

#pragma unroll
        for (int e = 0; e < 8; ++e) {
            const float mx = mixv[e];
#pragma unroll
            for (int h = 0; h < 2; ++h) {
                uint32_t d[32];
                asm volatile("tcgen05.ld.sync.aligned.32x32b.x32.b32 "
                    "{%0,%1,%2,%3,%4,%5,%6,%7,%8,%9,%10,%11,%12,%13,%14,%15,"
                    "%16,%17,%18,%19,%20,%21,%22,%23,%24,%25,%26,%27,%28,%29,%30,%31}, [%32];"
                    : "=r"(d[0]),"=r"(d[1]),"=r"(d[2]),"=r"(d[3]),"=r"(d[4]),"=r"(d[5]),
                      "=r"(d[6]),"=r"(d[7]),"=r"(d[8]),"=r"(d[9]),"=r"(d[10]),"=r"(d[11]),
                      "=r"(d[12]),"=r"(d[13]),"=r"(d[14]),"=r"(d[15]),"=r"(d[16]),"=r"(d[17]),
                      "=r"(d[18]),"=r"(d[19]),"=r"(d[20]),"=r"(d[21]),"=r"(d[22]),"=r"(d[23]),
                      "=r"(d[24]),"=r"(d[25]),"=r"(d[26]),"=r"(d[27]),"=r"(d[28]),"=r"(d[29]),
                      "=r"(d[30]),"=r"(d[31]) : "r"(tmem + e * 64 + h * 32));
                asm volatile("tcgen05.wait::ld.sync.aligned;" ::: "memory");
#pragma unroll
                for (int c = 0; c < 32; ++c) {
                    const float z = __uint_as_float(d[c]) + bgs[e * 64 + h * 32 + c];
                    accO[h * 32 + c] += mx / (1.0f + __expf(-z));
                }
            }
        }

        float* orow = out + (size_t)m * D_DIM + n0;
#pragma unroll
        for (int v = 0; v < 16; ++v) {
            float4 o = make_float4(accO[4 * v], accO[4 * v + 1],
                                   accO[4 * v + 2], accO[4 * v + 3]);
            __stcs((float4*)(orow + 4 * v), o);
        }
    }

    __syncthreads();
    if (wid == 6)
        asm volatile("tcgen05.dealloc.cta_group::1.sync.aligned.b32 %0, %1;"
            :: "r"(tmem), "r"(512));
#endif // HAS_TCGEN05
}

// ===========================================================================
// Kernel F: warp-level tf32 mma.sync fallback (active on family-generic cubin)
//   CTA tile 128x128, 8 warps (2x4), warp tile 64x32, m16n8k8, cp.async 2-stage.
// ===========================================================================
#define F_BM 128
#define F_BN 128
#define F_BK 16
#define F_ST 20   // padded smem row stride (floats) -> conflict-free frag LDS

__global__ __launch_bounds__(256, 1) void moe_gate_mma(
    const float* __restrict__ x,
    const float* __restrict__ Wg,
    const float* __restrict__ bg,
    float* __restrict__ out)
{
#if !HAS_TCGEN05
    __shared__ __align__(16) float As[2 * F_BM * F_ST];
    __shared__ __align__(16) float Bs[2 * F_BM * F_ST];
    __shared__ __align__(16) float mixs[F_BM * E_DIM];

    const int tid = threadIdx.x;
    const int warp = tid >> 5, lane = tid & 31;
    const int wm = (warp & 1) * 64;
    const int wn = (warp >> 1) * 32;
    const int g = lane >> 2, tg = lane & 3;
    const int m0 = blockIdx.y * F_BM, n0 = blockIdx.x * F_BN;

    const uint32_t sAs = smem_u32(As);
    const uint32_t sBs = smem_u32(Bs);

    // stage mix tile: 128x8 floats = 256 float4
    ((float4*)mixs)[tid] = ((const float4*)(g_mix + (size_t)m0 * E_DIM))[tid];
    __syncthreads();

    float accOut[4][4][4];
#pragma unroll
    for (int a = 0; a < 4; ++a)
#pragma unroll
        for (int b = 0; b < 4; ++b)
#pragma unroll
            for (int c = 0; c < 4; ++c) accOut[a][b][c] = 0.0f;

#define F_LOAD_STAGE(st, k0, Bsrc) do {                                          \
    _Pragma("unroll")                                                            \
    for (int it = 0; it < 2; ++it) {                                             \
        const int i = tid + it * 256;                                            \
        const int r = i >> 2, q = i & 3;                                         \
        CP_ASYNC16(sAs + (uint32_t)(((st) * F_BM * F_ST + r * F_ST + q * 4) * 4),\
                   x + (size_t)(m0 + r) * D_DIM + (k0) + q * 4);                 \
        CP_ASYNC16(sBs + (uint32_t)(((st) * F_BM * F_ST + r * F_ST + q * 4) * 4),\
                   (Bsrc) + (size_t)r * D_DIM + (k0) + q * 4);                   \
    }                                                                            \
    asm volatile("cp.async.commit_group;" ::: "memory");                         \
} while (0)

    for (int e = 0; e < E_DIM; ++e) {
        const float* Bsrc = Wg + (size_t)e * D_DIM * D_DIM + (size_t)n0 * D_DIM;

        float acc[4][4][4];
#pragma unroll
        for (int a = 0; a < 4; ++a)
#pragma unroll
            for (int b = 0; b < 4; ++b)
#pragma unroll
                for (int c = 0; c < 4; ++c) acc[a][b][c] = 0.0f;

        F_LOAD_STAGE(0, 0, Bsrc);

        for (int ks = 0; ks < D_DIM / F_BK; ++ks) {
            const int cur = ks & 1;
            if (ks < D_DIM / F_BK - 1) {
                F_LOAD_STAGE(cur ^ 1, (ks + 1) * F_BK, Bsrc);
                asm volatile("cp.async.wait_group 1;" ::: "memory");
            } else {
                asm volatile("cp.async.wait_group 0;" ::: "memory");
            }
            __syncthreads();

            const float* Af = As + cur * F_BM * F_ST;
            const float* Bf = Bs + cur * F_BM * F_ST;
#pragma unroll
            for (int kk = 0; kk < F_BK; kk += 8) {
                uint32_t afr[4][4], bfr[4][2];
#pragma unroll
                for (int mf = 0; mf < 4; ++mf) {
                    const int r = wm + mf * 16 + g;
                    afr[mf][0] = f2tf32(Af[r * F_ST + kk + tg]);
                    afr[mf][1] = f2tf32(Af[(r + 8) * F_ST + kk + tg]);
                    afr[mf][2] = f2tf32(Af[r * F_ST + kk + tg + 4]);
                    afr[mf][3] = f2tf32(Af[(r + 8) * F_ST + kk + tg + 4]);
                }
#pragma unroll
                for (int nf = 0; nf < 4; ++nf) {
                    const int c = wn + nf * 8 + g;
                    bfr[nf][0] = f2tf32(Bf[c * F_ST + kk + tg]);
                    bfr[nf][1] = f2tf32(Bf[c * F_ST + kk + tg + 4]);
                }
#pragma unroll
                for (int mf = 0; mf < 4; ++mf)
#pragma unroll
                    for (int nf = 0; nf < 4; ++nf)
                        mma16n8k8(acc[mf][nf], afr[mf], bfr[nf]);
            }
            __syncthreads();
        }

        // fold: accOut += mix[m,e] * sigmoid(acc + bg[e,n])
#pragma unroll
        for (int mf = 0; mf < 4; ++mf) {
            const int r = wm + mf * 16 + g;
            const float mx0 = mixs[r * E_DIM + e];
            const float mx1 = mixs[(r + 8) * E_DIM + e];
#pragma unroll
            for (int nf = 0; nf < 4; ++nf) {
                const int c = wn + nf * 8 + 2 * tg;
                const float b0 = __ldg(bg + (size_t)e * D_DIM + n0 + c);
                const float b1 = __ldg(bg + (size_t)e * D_DIM + n0 + c + 1);
                accOut[mf][nf][0] += mx0 / (1.0f + __expf(-(acc[mf][nf][0] + b0)));
                accOut[mf][nf][1] += mx0 / (1.0f + __expf(-(acc[mf][nf][1] + b1)));
                accOut[mf][nf][2] += mx1 / (1.0f + __expf(-(acc[mf][nf][2] + b0)));
                accOut[mf][nf][3] += mx1 / (1.0f + __expf(-(acc[mf][nf][3] + b1)));
            }
        }
    }

    // write 128x128 tile
#pragma unroll
    for (int mf = 0; mf < 4; ++mf) {
        const int r0 = m0 + wm + mf * 16 + g;
#pragma unroll
        for (int nf = 0; nf < 4; ++nf) {
            const int c = n0 + wn + nf * 8 + 2 * tg;
            *(float2*)(out + (size_t)r0 * D_DIM + c) =
                make_float2(accOut[mf][nf][0], accOut[mf][nf][1]);
            *(float2*)(out + (size_t)(r0 + 8) * D_DIM + c) =
                make_float2(accOut[mf][nf][2], accOut[mf][nf][3]);
        }
    }
#endif // !HAS_TCGEN05
}

// ===========================================================================
// Inputs: x, Wg, bg, Wf, bf, Wt, bt, alpha, num
// ===========================================================================
extern "C" void kernel_launch(void* const* d_in, const int* in_sizes, int n_in,
                              void* d_out, int out_size)
{
    const float* x     = (const float*)d_in[0];
    const float* Wg    = (const float*)d_in[1];
    const float* bg    = (const float*)d_in[2];
    const float* Wf    = (const float*)d_in[3];
    const float* bf    = (const float*)d_in[4];
    const float* Wt    = (const float*)d_in[5];
    const float* bt    = (const float*)d_in[6];
    const float* alpha = (const float*)d_in[7];
    float* out = (float*)d_out;

    const int BT = in_sizes[0] / D_DIM;   // 16384

    cudaFuncSetAttribute(moe_gate_tc,
                         cudaFuncAttributeMaxDynamicSharedMemorySize, SMEM_TOTAL);

    routing_kernel<<<(BT + 3) / 4, 128>>>(x, Wf, bf, Wt, bt, alpha, BT);

    // tcgen05 path (no-op on family-generic cubin)
    dim3 gridT(D_DIM / T_BN, BT / T_BM);           // (16, 128)
    moe_gate_tc<<<gridT, 256, SMEM_TOTAL>>>(x, Wg, bg, out);

    // mma.sync fallback (no-op on arch-specific cubin)
    dim3 gridF(D_DIM / F_BN, BT / F_BM);           // (8, 128)
    moe_gate_mma<<<gridF, 256>>>(x, Wg, bg, out);
}